// round 11
// baseline (speedup 1.0000x reference)
#include <cuda_runtime.h>
#include <cuda_fp16.h>
#include <cstdint>

#define N_FEAT 32
#define N_COLS 128          // 4 relations * 32 output features
#define MAX_NODES 524288
#define MAX_EDGES 4194304
#define TN 128              // nodes per transform block

#define XH_STRIDE 40
#define WH_STRIDE 136
#define ST_STRIDE 136

// Scratch. xt is REL-MAJOR: xt[rel][node][32] fp16 (4 x 32 MB).
__device__ __half g_xt[(size_t)4 * MAX_NODES * N_FEAT];
__device__ __half g_agg1[(size_t)MAX_NODES * N_FEAT];
__device__ __half g_agg2[(size_t)MAX_NODES * N_FEAT];
__device__ unsigned int g_esrc[MAX_EDGES];   // src, binned by rel
__device__ unsigned int g_edst[MAX_EDGES];   // dst, binned by rel
__device__ int g_cnt4[4];
__device__ int g_off[5];
__device__ int g_cursor[4];
__device__ unsigned int g_done;

// ---------------------------------------------------------------------------
// Rel histogram; last block computes offsets (exclusive scan of 4) + cursor.
// g_cnt4/g_done zeroed by transform_k<false> (launch 0).
// ---------------------------------------------------------------------------
__global__ void __launch_bounds__(256) hist_k(const int* __restrict__ et, int ne)
{
    __shared__ int h[4];
    if (threadIdx.x < 4) h[threadIdx.x] = 0;
    __syncthreads();

    const int e = blockIdx.x * 256 + threadIdx.x;
    if (e < ne) atomicAdd(&h[__ldg(et + e)], 1);
    __syncthreads();

    if (threadIdx.x < 4 && h[threadIdx.x])
        atomicAdd(&g_cnt4[threadIdx.x], h[threadIdx.x]);
    __threadfence();
    __syncthreads();

    if (threadIdx.x == 0) {
        const unsigned int t = atomicAdd(&g_done, 1u);
        if (t == gridDim.x - 1) {
            int o = 0;
            #pragma unroll
            for (int r = 0; r < 4; r++) {
                g_off[r] = o; g_cursor[r] = o; o += g_cnt4[r];
            }
            g_off[4] = o;
            g_done = 0;
        }
    }
}

// ---------------------------------------------------------------------------
// Reorder edges into rel bins (block-aggregated cursor updates).
// ---------------------------------------------------------------------------
__global__ void __launch_bounds__(256) reorder_k(
    const int* __restrict__ src, const int* __restrict__ dst,
    const int* __restrict__ et,
    unsigned int* __restrict__ esrc, unsigned int* __restrict__ edst, int ne)
{
    __shared__ int h[4];
    __shared__ int base[4];
    if (threadIdx.x < 4) h[threadIdx.x] = 0;
    __syncthreads();

    const int e = blockIdx.x * 256 + threadIdx.x;
    const bool valid = (e < ne);
    int r = 0, s = 0, d = 0, rank = 0;
    if (valid) {
        r = __ldg(et + e); s = __ldg(src + e); d = __ldg(dst + e);
        rank = atomicAdd(&h[r], 1);
    }
    __syncthreads();
    if (threadIdx.x < 4)
        base[threadIdx.x] = atomicAdd(&g_cursor[threadIdx.x], h[threadIdx.x]);
    __syncthreads();
    if (valid) {
        const int pos = base[r] + rank;
        esrc[pos] = (unsigned int)s;
        edst[pos] = (unsigned int)d;
    }
}

// ---------------------------------------------------------------------------
// Binned scatter: edges sorted by rel -> gather working set = one 32 MB rel
// plane (L2-resident). 4 lanes/edge, one red.add.v4.f16x2 each.
// ---------------------------------------------------------------------------
__global__ void __launch_bounds__(256) scatter_k(
    const __half* __restrict__ xt,
    const unsigned int* __restrict__ esrc, const unsigned int* __restrict__ edst,
    __half* __restrict__ agg, int ne, int nnodes)
{
    const int t = blockIdx.x * 256 + threadIdx.x;
    const int e = t >> 2;
    if (e >= ne) return;
    const int q = t & 3;

    const int o1 = __ldg(&g_off[1]), o2 = __ldg(&g_off[2]), o3 = __ldg(&g_off[3]);
    const int r = (e >= o1) + (e >= o2) + (e >= o3);

    const unsigned int s = __ldg(esrc + e);
    const unsigned int d = __ldg(edst + e);

    const uint4 p = *reinterpret_cast<const uint4*>(
        xt + (((size_t)r * nnodes + s) << 5) + q * 8);

    __half* ap = agg + ((size_t)d << 5) + q * 8;
    asm volatile("red.global.add.noftz.v4.f16x2 [%0], {%1, %2, %3, %4};"
                 :: "l"(ap), "r"(p.x), "r"(p.y), "r"(p.z), "r"(p.w)
                 : "memory");
}

// ---------------------------------------------------------------------------
// Tensor-core transform; epilogue writes REL-MAJOR xt planes.
// Layer 1 only: piggyback FULL zeroing of agg1/agg2 (grid-stride over
// nnodes*4 uint4 each — the R10 bug was covering only half) + counters.
// PRE_ACT: in is fp16 agg (node-major 32), apply relu(v + b[d]).
// ---------------------------------------------------------------------------
template<bool PRE_ACT>
__global__ void __launch_bounds__(256) transform_k(
    const void* __restrict__ xin_, const float* __restrict__ W,
    const float* __restrict__ b, __half* __restrict__ xt,
    __half* __restrict__ z1, __half* __restrict__ z2, int nnodes)
{
    __shared__ __align__(16) unsigned char sm[TN * ST_STRIDE * 2]; // 34816 B
    __half* xh    = reinterpret_cast<__half*>(sm);
    __half* wh    = reinterpret_cast<__half*>(sm + 10240);
    __half* stage = reinterpret_cast<__half*>(sm);

    const int tid  = threadIdx.x;
    const int base = blockIdx.x * TN;

    if (!PRE_ACT) {
        // agg buffers are nnodes*32 halfs = nnodes*4 uint4 EACH.
        const int gtid   = blockIdx.x * 256 + tid;
        const int stride = (int)gridDim.x * 256;     // = nnodes*2 threads
        const int nu4    = nnodes * 4;
        uint4* a1 = reinterpret_cast<uint4*>(z1);
        uint4* a2 = reinterpret_cast<uint4*>(z2);
        const uint4 zz = make_uint4(0u, 0u, 0u, 0u);
        for (int i = gtid; i < nu4; i += stride) { a1[i] = zz; a2[i] = zz; }
        if (gtid == 0) {
            g_cnt4[0] = g_cnt4[1] = g_cnt4[2] = g_cnt4[3] = 0;
            g_done = 0u;
        }
    }

    // Fill W smem: wh[d][r*32+o] = half(W[r][d][o]).
    for (int f = tid; f < 1024; f += 256) {
        const float4 v = reinterpret_cast<const float4*>(W)[f];
        const int r = f >> 8, d = (f >> 3) & 31, o4 = f & 7;
        __half* p = &wh[d * WH_STRIDE + r * 32 + o4 * 4];
        p[0] = __float2half_rn(v.x); p[1] = __float2half_rn(v.y);
        p[2] = __float2half_rn(v.z); p[3] = __float2half_rn(v.w);
    }

    // Fill x tile.
    if (PRE_ACT) {
        const __half* xin = reinterpret_cast<const __half*>(xin_);
        for (int f = tid; f < TN * 4; f += 256) {
            const int i = f >> 2, kq = f & 3;
            const uint4 pk = *reinterpret_cast<const uint4*>(
                xin + (size_t)(base + i) * N_FEAT + kq * 8);
            const __half2* hp = reinterpret_cast<const __half2*>(&pk);
            const float4 b0 = __ldg(reinterpret_cast<const float4*>(b + kq * 8));
            const float4 b1 = __ldg(reinterpret_cast<const float4*>(b + kq * 8 + 4));
            const float bb[8] = {b0.x, b0.y, b0.z, b0.w, b1.x, b1.y, b1.z, b1.w};
            __half* d = &xh[i * XH_STRIDE + kq * 8];
            #pragma unroll
            for (int j = 0; j < 4; j++) {
                float2 fv = __half22float2(hp[j]);
                fv.x = fmaxf(fv.x + bb[j * 2 + 0], 0.f);
                fv.y = fmaxf(fv.y + bb[j * 2 + 1], 0.f);
                *reinterpret_cast<__half2*>(d + j * 2) = __floats2half2_rn(fv.x, fv.y);
            }
        }
    } else {
        const float4* xin4 = reinterpret_cast<const float4*>(
            reinterpret_cast<const float*>(xin_) + (size_t)base * N_FEAT);
        for (int f = tid; f < TN * 8; f += 256) {
            const float4 v = xin4[f];
            const int i = f >> 3, kq = f & 7;
            __half* d = &xh[i * XH_STRIDE + kq * 4];
            *reinterpret_cast<__half2*>(d)     = __floats2half2_rn(v.x, v.y);
            *reinterpret_cast<__half2*>(d + 2) = __floats2half2_rn(v.z, v.w);
        }
    }
    __syncthreads();

    const int w    = tid >> 5;
    const int lane = tid & 31;
    const int m0   = w * 16;

    uint32_t a[2][4];
    #pragma unroll
    for (int s = 0; s < 2; s++) {
        const int row = m0 + (lane & 15);
        const int col = s * 16 + ((lane >> 4) << 3);
        const uint32_t addr =
            (uint32_t)__cvta_generic_to_shared(&xh[row * XH_STRIDE + col]);
        asm volatile("ldmatrix.sync.aligned.m8n8.x4.shared.b16 {%0,%1,%2,%3}, [%4];"
                     : "=r"(a[s][0]), "=r"(a[s][1]), "=r"(a[s][2]), "=r"(a[s][3])
                     : "r"(addr));
    }

    float acc[16][4];
    #pragma unroll
    for (int j = 0; j < 16; j++)
        #pragma unroll
        for (int q = 0; q < 4; q++) acc[j][q] = 0.f;

    #pragma unroll
    for (int j = 0; j < 16; j++) {
        #pragma unroll
        for (int s = 0; s < 2; s++) {
            const int krow = s * 16 + (lane & 15);
            const uint32_t baddr =
                (uint32_t)__cvta_generic_to_shared(&wh[krow * WH_STRIDE + j * 8]);
            uint32_t b0, b1;
            asm volatile("ldmatrix.sync.aligned.m8n8.x2.trans.shared.b16 {%0,%1}, [%2];"
                         : "=r"(b0), "=r"(b1) : "r"(baddr));
            asm volatile(
                "mma.sync.aligned.m16n8k16.row.col.f32.f16.f16.f32 "
                "{%0,%1,%2,%3}, {%4,%5,%6,%7}, {%8,%9}, {%0,%1,%2,%3};"
                : "+f"(acc[j][0]), "+f"(acc[j][1]), "+f"(acc[j][2]), "+f"(acc[j][3])
                : "r"(a[s][0]), "r"(a[s][1]), "r"(a[s][2]), "r"(a[s][3]),
                  "r"(b0), "r"(b1));
        }
    }
    __syncthreads();

    const int g  = lane >> 2;
    const int t4 = lane & 3;
    #pragma unroll
    for (int j = 0; j < 16; j++) {
        *reinterpret_cast<__half2*>(&stage[(m0 + g) * ST_STRIDE + j * 8 + t4 * 2]) =
            __floats2half2_rn(acc[j][0], acc[j][1]);
        *reinterpret_cast<__half2*>(&stage[(m0 + g + 8) * ST_STRIDE + j * 8 + t4 * 2]) =
            __floats2half2_rn(acc[j][2], acc[j][3]);
    }
    __syncthreads();

    // Store: rel plane = ch>>2, 16B chunk = ch&3.
    for (int f = tid; f < TN * 16; f += 256) {
        const int row = f >> 4, ch = f & 15;
        const int rel = ch >> 2, c4 = ch & 3;
        const uint4 v = *reinterpret_cast<const uint4*>(&stage[row * ST_STRIDE + ch * 8]);
        *reinterpret_cast<uint4*>(
            xt + (((size_t)rel * nnodes + base + row) << 5) + c4 * 8) = v;
    }
}

// ---------------------------------------------------------------------------
// Pool: out[g][c] = mean_{i<32} relu(agg2[g*32+i][c] + b[c]).
// ---------------------------------------------------------------------------
__global__ void __launch_bounds__(256) pool_k(
    const __half* __restrict__ agg, const float* __restrict__ b,
    float* __restrict__ out, int nnodes)
{
    const int t = blockIdx.x * blockDim.x + threadIdx.x;
    if (t >= nnodes) return;
    const int c = t & 31;
    const int g = t >> 5;
    const float bc = __ldg(b + c);
    const __half* p = agg + (size_t)g * 32 * N_FEAT + c;
    float s = 0.f;
    #pragma unroll
    for (int i = 0; i < 32; i++)
        s += fmaxf(__half2float(p[i * N_FEAT]) + bc, 0.f);
    out[t] = s * (1.0f / 32.0f);
}

// ---------------------------------------------------------------------------
// Launch order: 0 tf<0>(+zero aggs/counters), 1 hist, 2 reorder,
// 3 scatter1 (<- ncu capture slot), 4 tf<1>, 5 scatter2, 6 pool.
// ---------------------------------------------------------------------------
extern "C" void kernel_launch(void* const* d_in, const int* in_sizes, int n_in,
                              void* d_out, int out_size)
{
    const float* x   = (const float*)d_in[0];
    const int*   src = (const int*)  d_in[1];
    const int*   dst = (const int*)  d_in[2];
    const int*   et  = (const int*)  d_in[3];
    const float* W   = (const float*)d_in[4];
    const float* b   = (const float*)d_in[5];

    const int nnodes = in_sizes[0] / N_FEAT;
    const int nedges = in_sizes[1];

    __half *xt, *agg1, *agg2;
    unsigned int *esrc, *edst;
    cudaGetSymbolAddress((void**)&xt,   g_xt);
    cudaGetSymbolAddress((void**)&agg1, g_agg1);
    cudaGetSymbolAddress((void**)&agg2, g_agg2);
    cudaGetSymbolAddress((void**)&esrc, g_esrc);
    cudaGetSymbolAddress((void**)&edst, g_edst);

    const int tf_blocks = nnodes / TN;
    const int eb_blocks = (nedges + 255) / 256;
    const int sc_blocks = (nedges * 4 + 255) / 256;

    // 0: Layer-1 transform (+ full zero of aggs/counters piggyback)
    transform_k<false><<<tf_blocks, 256>>>(x, W, b, xt, agg1, agg2, nnodes);
    // 1-2: rel binning
    hist_k<<<eb_blocks, 256>>>(et, nedges);
    reorder_k<<<eb_blocks, 256>>>(src, dst, et, esrc, edst, nedges);
    // 3: Layer-1 scatter (captured by ncu)
    scatter_k<<<sc_blocks, 256>>>(xt, esrc, edst, agg1, nedges, nnodes);
    // 4-5: Layer 2
    transform_k<true><<<tf_blocks, 256>>>(agg1, W, b, xt, nullptr, nullptr, nnodes);
    scatter_k<<<sc_blocks, 256>>>(xt, esrc, edst, agg2, nedges, nnodes);
    // 6: Pool
    pool_k<<<(nnodes + 255) / 256, 256>>>(agg2, b, (float*)d_out, nnodes);
    (void)n_in; (void)out_size;
}

// round 12
// speedup vs baseline: 1.0948x; 1.0948x over previous
#include <cuda_runtime.h>
#include <cuda_fp16.h>
#include <cstdint>

#define N_FEAT 32
#define MAX_NODES 524288
#define MAX_EDGES 4194304
#define TN 128

#define XH_STRIDE 40
#define WH_STRIDE 136
#define ST_STRIDE 136

// Scratch. xt REL-MAJOR: xt[rel][node][32] fp16 (4 x 32 MB).
__device__ __half g_xt[(size_t)4 * MAX_NODES * N_FEAT];
__device__ __half g_agg1[(size_t)MAX_NODES * N_FEAT];
__device__ __half g_agg2[(size_t)MAX_NODES * N_FEAT];
__device__ uint2  g_esd[MAX_EDGES];          // (src,dst) binned by rel
__device__ int g_cnt4[4];
__device__ int g_off[5];
__device__ int g_cursor[4];
__device__ unsigned int g_done;

// ---------------------------------------------------------------------------
// Rel histogram, warp-aggregated (match_any -> <=4 smem atomics per WARP).
// Last block computes offsets + cursors. Counters zeroed by tf<false>.
// ---------------------------------------------------------------------------
__global__ void __launch_bounds__(256) hist_k(const int* __restrict__ et, int ne)
{
    __shared__ int h[4];
    if (threadIdx.x < 4) h[threadIdx.x] = 0;
    __syncthreads();

    const int e = blockIdx.x * 256 + threadIdx.x;
    if (e < ne) {
        const int r = __ldg(et + e);
        const unsigned int mask = __match_any_sync(__activemask(), r);
        const unsigned int lt   = (1u << (threadIdx.x & 31)) - 1u;
        if ((mask & lt) == 0u)                       // leader of this r-group
            atomicAdd(&h[r], __popc(mask));
    }
    __syncthreads();

    if (threadIdx.x < 4 && h[threadIdx.x])
        atomicAdd(&g_cnt4[threadIdx.x], h[threadIdx.x]);
    __threadfence();
    __syncthreads();

    if (threadIdx.x == 0) {
        const unsigned int t = atomicAdd(&g_done, 1u);
        if (t == gridDim.x - 1) {
            int o = 0;
            #pragma unroll
            for (int r = 0; r < 4; r++) {
                g_off[r] = o; g_cursor[r] = o; o += g_cnt4[r];
            }
            g_off[4] = o;
            g_done = 0;
        }
    }
}

// ---------------------------------------------------------------------------
// Reorder into rel bins; warp-aggregated ranking, block-aggregated cursors.
// Writes packed (src,dst) uint2.
// ---------------------------------------------------------------------------
__global__ void __launch_bounds__(256) reorder_k(
    const int* __restrict__ src, const int* __restrict__ dst,
    const int* __restrict__ et, uint2* __restrict__ esd, int ne)
{
    __shared__ int h[4];      // block-local counts
    __shared__ int base[4];   // global base per rel
    if (threadIdx.x < 4) h[threadIdx.x] = 0;
    __syncthreads();

    const int e = blockIdx.x * 256 + threadIdx.x;
    int r = 0, pos_local = 0;
    uint2 sd = make_uint2(0u, 0u);
    const bool valid = (e < ne);
    if (valid) {
        r = __ldg(et + e);
        sd.x = (unsigned int)__ldg(src + e);
        sd.y = (unsigned int)__ldg(dst + e);
        const unsigned int mask = __match_any_sync(__activemask(), r);
        const unsigned int lt   = (1u << (threadIdx.x & 31)) - 1u;
        const int rank = __popc(mask & lt);
        int wbase = 0;
        if (rank == 0) wbase = atomicAdd(&h[r], __popc(mask));
        const int leader = __ffs(mask) - 1;
        wbase = __shfl_sync(0xffffffffu, wbase, leader);
        pos_local = wbase + rank;
    }
    __syncthreads();
    if (threadIdx.x < 4)
        base[threadIdx.x] = atomicAdd(&g_cursor[threadIdx.x], h[threadIdx.x]);
    __syncthreads();
    if (valid) esd[base[r] + pos_local] = sd;
}

// ---------------------------------------------------------------------------
// Binned scatter: 2 edges per thread, 4 lanes per edge. Two independent
// gathers in flight, then two REDs. Indices = one uint2 load per edge.
// ---------------------------------------------------------------------------
__global__ void __launch_bounds__(256) scatter_k(
    const __half* __restrict__ xt, const uint2* __restrict__ esd,
    __half* __restrict__ agg, int ne, int nnodes)
{
    const int t = blockIdx.x * 256 + threadIdx.x;
    const int p = t >> 2;            // pair index
    const int q = t & 3;
    const int e0 = p * 2;
    if (e0 >= ne) return;
    const int e1 = e0 + 1;

    const int o1 = __ldg(&g_off[1]), o2 = __ldg(&g_off[2]), o3 = __ldg(&g_off[3]);
    const int r0 = (e0 >= o1) + (e0 >= o2) + (e0 >= o3);
    const int r1 = (e1 >= o1) + (e1 >= o2) + (e1 >= o3);

    const uint2 sd0 = __ldg(esd + e0);
    const uint2 sd1 = __ldg(esd + e1);

    const uint4 v0 = *reinterpret_cast<const uint4*>(
        xt + (((size_t)r0 * nnodes + sd0.x) << 5) + q * 8);
    const uint4 v1 = *reinterpret_cast<const uint4*>(
        xt + (((size_t)r1 * nnodes + sd1.x) << 5) + q * 8);

    __half* a0 = agg + ((size_t)sd0.y << 5) + q * 8;
    asm volatile("red.global.add.noftz.v4.f16x2 [%0], {%1, %2, %3, %4};"
                 :: "l"(a0), "r"(v0.x), "r"(v0.y), "r"(v0.z), "r"(v0.w) : "memory");
    __half* a1 = agg + ((size_t)sd1.y << 5) + q * 8;
    asm volatile("red.global.add.noftz.v4.f16x2 [%0], {%1, %2, %3, %4};"
                 :: "l"(a1), "r"(v1.x), "r"(v1.y), "r"(v1.z), "r"(v1.w) : "memory");
}

// ---------------------------------------------------------------------------
// Tensor-core transform; rel-major epilogue, fully coalesced (warp writes
// 512 B contiguous per plane). zbuf: agg buffer to zero (agg1 in layer 1,
// agg2 in layer 2); layer 1 also resets counters.
// ---------------------------------------------------------------------------
template<bool PRE_ACT>
__global__ void __launch_bounds__(256) transform_k(
    const void* __restrict__ xin_, const float* __restrict__ W,
    const float* __restrict__ b, __half* __restrict__ xt,
    __half* __restrict__ zbuf, int nnodes)
{
    __shared__ __align__(16) unsigned char sm[TN * ST_STRIDE * 2]; // 34816 B
    __half* xh    = reinterpret_cast<__half*>(sm);
    __half* wh    = reinterpret_cast<__half*>(sm + 10240);
    __half* stage = reinterpret_cast<__half*>(sm);

    const int tid  = threadIdx.x;
    const int base = blockIdx.x * TN;

    {   // zero one agg buffer: nnodes*4 uint4, grid has nnodes*2 threads.
        const int gtid = blockIdx.x * 256 + tid;
        uint4* a = reinterpret_cast<uint4*>(zbuf);
        const uint4 zz = make_uint4(0u, 0u, 0u, 0u);
        a[gtid] = zz;
        a[gtid + nnodes * 2] = zz;
        if (!PRE_ACT && gtid == 0) {
            g_cnt4[0] = g_cnt4[1] = g_cnt4[2] = g_cnt4[3] = 0;
            g_done = 0u;
        }
    }

    // W smem: wh[d][r*32+o] = half(W[r][d][o]).
    for (int f = tid; f < 1024; f += 256) {
        const float4 v = reinterpret_cast<const float4*>(W)[f];
        const int r = f >> 8, d = (f >> 3) & 31, o4 = f & 7;
        __half* p = &wh[d * WH_STRIDE + r * 32 + o4 * 4];
        p[0] = __float2half_rn(v.x); p[1] = __float2half_rn(v.y);
        p[2] = __float2half_rn(v.z); p[3] = __float2half_rn(v.w);
    }

    // x tile.
    if (PRE_ACT) {
        const __half* xin = reinterpret_cast<const __half*>(xin_);
        for (int f = tid; f < TN * 4; f += 256) {
            const int i = f >> 2, kq = f & 3;
            const uint4 pk = *reinterpret_cast<const uint4*>(
                xin + (size_t)(base + i) * N_FEAT + kq * 8);
            const __half2* hp = reinterpret_cast<const __half2*>(&pk);
            const float4 b0 = __ldg(reinterpret_cast<const float4*>(b + kq * 8));
            const float4 b1 = __ldg(reinterpret_cast<const float4*>(b + kq * 8 + 4));
            const float bb[8] = {b0.x, b0.y, b0.z, b0.w, b1.x, b1.y, b1.z, b1.w};
            __half* d = &xh[i * XH_STRIDE + kq * 8];
            #pragma unroll
            for (int j = 0; j < 4; j++) {
                float2 fv = __half22float2(hp[j]);
                fv.x = fmaxf(fv.x + bb[j * 2 + 0], 0.f);
                fv.y = fmaxf(fv.y + bb[j * 2 + 1], 0.f);
                *reinterpret_cast<__half2*>(d + j * 2) = __floats2half2_rn(fv.x, fv.y);
            }
        }
    } else {
        const float4* xin4 = reinterpret_cast<const float4*>(
            reinterpret_cast<const float*>(xin_) + (size_t)base * N_FEAT);
        for (int f = tid; f < TN * 8; f += 256) {
            const float4 v = xin4[f];
            const int i = f >> 3, kq = f & 7;
            __half* d = &xh[i * XH_STRIDE + kq * 4];
            *reinterpret_cast<__half2*>(d)     = __floats2half2_rn(v.x, v.y);
            *reinterpret_cast<__half2*>(d + 2) = __floats2half2_rn(v.z, v.w);
        }
    }
    __syncthreads();

    const int w    = tid >> 5;
    const int lane = tid & 31;
    const int m0   = w * 16;

    uint32_t a[2][4];
    #pragma unroll
    for (int s = 0; s < 2; s++) {
        const int row = m0 + (lane & 15);
        const int col = s * 16 + ((lane >> 4) << 3);
        const uint32_t addr =
            (uint32_t)__cvta_generic_to_shared(&xh[row * XH_STRIDE + col]);
        asm volatile("ldmatrix.sync.aligned.m8n8.x4.shared.b16 {%0,%1,%2,%3}, [%4];"
                     : "=r"(a[s][0]), "=r"(a[s][1]), "=r"(a[s][2]), "=r"(a[s][3])
                     : "r"(addr));
    }

    float acc[16][4];
    #pragma unroll
    for (int j = 0; j < 16; j++)
        #pragma unroll
        for (int q = 0; q < 4; q++) acc[j][q] = 0.f;

    #pragma unroll
    for (int j = 0; j < 16; j++) {
        #pragma unroll
        for (int s = 0; s < 2; s++) {
            const int krow = s * 16 + (lane & 15);
            const uint32_t baddr =
                (uint32_t)__cvta_generic_to_shared(&wh[krow * WH_STRIDE + j * 8]);
            uint32_t b0, b1;
            asm volatile("ldmatrix.sync.aligned.m8n8.x2.trans.shared.b16 {%0,%1}, [%2];"
                         : "=r"(b0), "=r"(b1) : "r"(baddr));
            asm volatile(
                "mma.sync.aligned.m16n8k16.row.col.f32.f16.f16.f32 "
                "{%0,%1,%2,%3}, {%4,%5,%6,%7}, {%8,%9}, {%0,%1,%2,%3};"
                : "+f"(acc[j][0]), "+f"(acc[j][1]), "+f"(acc[j][2]), "+f"(acc[j][3])
                : "r"(a[s][0]), "r"(a[s][1]), "r"(a[s][2]), "r"(a[s][3]),
                  "r"(b0), "r"(b1));
        }
    }
    __syncthreads();

    const int g  = lane >> 2;
    const int t4 = lane & 3;
    #pragma unroll
    for (int j = 0; j < 16; j++) {
        *reinterpret_cast<__half2*>(&stage[(m0 + g) * ST_STRIDE + j * 8 + t4 * 2]) =
            __floats2half2_rn(acc[j][0], acc[j][1]);
        *reinterpret_cast<__half2*>(&stage[(m0 + g + 8) * ST_STRIDE + j * 8 + t4 * 2]) =
            __floats2half2_rn(acc[j][2], acc[j][3]);
    }
    __syncthreads();

    // Coalesced rel-major store: f decodes (rel, row, c4) so a warp writes
    // 8 rows x 64 B contiguous within one plane.
    for (int f = tid; f < TN * 16; f += 256) {
        const int rel = f >> 9, row = (f >> 2) & 127, c4 = f & 3;
        const uint4 v = *reinterpret_cast<const uint4*>(
            &stage[row * ST_STRIDE + (rel * 4 + c4) * 8]);
        *reinterpret_cast<uint4*>(
            xt + (((size_t)rel * nnodes + base + row) << 5) + c4 * 8) = v;
    }
}

// ---------------------------------------------------------------------------
// Pool: out[g][c] = mean_{i<32} relu(agg2[g*32+i][c] + b[c]).
// ---------------------------------------------------------------------------
__global__ void __launch_bounds__(256) pool_k(
    const __half* __restrict__ agg, const float* __restrict__ b,
    float* __restrict__ out, int nnodes)
{
    const int t = blockIdx.x * blockDim.x + threadIdx.x;
    if (t >= nnodes) return;
    const int c = t & 31;
    const int g = t >> 5;
    const float bc = __ldg(b + c);
    const __half* p = agg + (size_t)g * 32 * N_FEAT + c;
    float s = 0.f;
    #pragma unroll
    for (int i = 0; i < 32; i++)
        s += fmaxf(__half2float(p[i * N_FEAT]) + bc, 0.f);
    out[t] = s * (1.0f / 32.0f);
}

// ---------------------------------------------------------------------------
// Launch order: 0 tf<0>(+zero agg1+counters), 1 hist, 2 reorder,
// 3 scatter1 (ncu capture slot), 4 tf<1>(+zero agg2), 5 scatter2, 6 pool.
// ---------------------------------------------------------------------------
extern "C" void kernel_launch(void* const* d_in, const int* in_sizes, int n_in,
                              void* d_out, int out_size)
{
    const float* x   = (const float*)d_in[0];
    const int*   src = (const int*)  d_in[1];
    const int*   dst = (const int*)  d_in[2];
    const int*   et  = (const int*)  d_in[3];
    const float* W   = (const float*)d_in[4];
    const float* b   = (const float*)d_in[5];

    const int nnodes = in_sizes[0] / N_FEAT;
    const int nedges = in_sizes[1];

    __half *xt, *agg1, *agg2; uint2 *esd;
    cudaGetSymbolAddress((void**)&xt,   g_xt);
    cudaGetSymbolAddress((void**)&agg1, g_agg1);
    cudaGetSymbolAddress((void**)&agg2, g_agg2);
    cudaGetSymbolAddress((void**)&esd,  g_esd);

    const int tf_blocks = nnodes / TN;
    const int eb_blocks = (nedges + 255) / 256;
    const int sc_blocks = (nedges * 2 + 255) / 256;   // 2 edges/thread, 4 lanes

    transform_k<false><<<tf_blocks, 256>>>(x, W, b, xt, agg1, nnodes);
    hist_k<<<eb_blocks, 256>>>(et, nedges);
    reorder_k<<<eb_blocks, 256>>>(src, dst, et, esd, nedges);
    scatter_k<<<sc_blocks, 256>>>(xt, esd, agg1, nedges, nnodes);
    transform_k<true><<<tf_blocks, 256>>>(agg1, W, b, xt, agg2, nnodes);
    scatter_k<<<sc_blocks, 256>>>(xt, esd, agg2, nedges, nnodes);
    pool_k<<<(nnodes + 255) / 256, 256>>>(agg2, b, (float*)d_out, nnodes);
    (void)n_in; (void)out_size;
}

// round 13
// speedup vs baseline: 1.1083x; 1.0123x over previous
#include <cuda_runtime.h>
#include <cuda_fp16.h>
#include <cstdint>

#define N_FEAT 32
#define MAX_NODES 524288
#define MAX_EDGES 4194304
#define TN 128

#define XH_STRIDE 40
#define WH_STRIDE 136
#define ST_STRIDE 136

// Scratch. xt REL-MAJOR: xt[rel][node][32] fp16 (4 x 32 MB).
__device__ __half g_xt[(size_t)4 * MAX_NODES * N_FEAT];
__device__ __half g_agg1[(size_t)MAX_NODES * N_FEAT];
__device__ __half g_agg2[(size_t)MAX_NODES * N_FEAT];
__device__ uint2  g_esd[MAX_EDGES];          // (src,dst) binned by rel
__device__ int g_cnt4[4];
__device__ int g_off[5];
__device__ int g_cursor[4];
__device__ unsigned int g_done;

// ---------------------------------------------------------------------------
// Rel histogram, warp-aggregated. Last block computes offsets + cursors.
// Counters zeroed by tf<false>.
// ---------------------------------------------------------------------------
__global__ void __launch_bounds__(256) hist_k(const int* __restrict__ et, int ne)
{
    __shared__ int h[4];
    if (threadIdx.x < 4) h[threadIdx.x] = 0;
    __syncthreads();

    const int e = blockIdx.x * 256 + threadIdx.x;
    if (e < ne) {
        const int r = __ldg(et + e);
        const unsigned int mask = __match_any_sync(__activemask(), r);
        const unsigned int lt   = (1u << (threadIdx.x & 31)) - 1u;
        if ((mask & lt) == 0u)
            atomicAdd(&h[r], __popc(mask));
    }
    __syncthreads();

    if (threadIdx.x < 4 && h[threadIdx.x])
        atomicAdd(&g_cnt4[threadIdx.x], h[threadIdx.x]);
    __threadfence();
    __syncthreads();

    if (threadIdx.x == 0) {
        const unsigned int t = atomicAdd(&g_done, 1u);
        if (t == gridDim.x - 1) {
            int o = 0;
            #pragma unroll
            for (int r = 0; r < 4; r++) {
                g_off[r] = o; g_cursor[r] = o; o += g_cnt4[r];
            }
            g_off[4] = o;
            g_done = 0;
        }
    }
}

// ---------------------------------------------------------------------------
// Reorder into rel bins; warp-aggregated ranking, block-aggregated cursors.
// ---------------------------------------------------------------------------
__global__ void __launch_bounds__(256) reorder_k(
    const int* __restrict__ src, const int* __restrict__ dst,
    const int* __restrict__ et, uint2* __restrict__ esd, int ne)
{
    __shared__ int h[4];
    __shared__ int base[4];
    if (threadIdx.x < 4) h[threadIdx.x] = 0;
    __syncthreads();

    const int e = blockIdx.x * 256 + threadIdx.x;
    int r = 0, pos_local = 0;
    uint2 sd = make_uint2(0u, 0u);
    const bool valid = (e < ne);
    if (valid) {
        r = __ldg(et + e);
        sd.x = (unsigned int)__ldg(src + e);
        sd.y = (unsigned int)__ldg(dst + e);
        const unsigned int mask = __match_any_sync(__activemask(), r);
        const unsigned int lt   = (1u << (threadIdx.x & 31)) - 1u;
        const int rank = __popc(mask & lt);
        int wbase = 0;
        if (rank == 0) wbase = atomicAdd(&h[r], __popc(mask));
        const int leader = __ffs(mask) - 1;
        wbase = __shfl_sync(0xffffffffu, wbase, leader);
        pos_local = wbase + rank;
    }
    __syncthreads();
    if (threadIdx.x < 4)
        base[threadIdx.x] = atomicAdd(&g_cursor[threadIdx.x], h[threadIdx.x]);
    __syncthreads();
    if (valid) esd[base[r] + pos_local] = sd;
}

// ---------------------------------------------------------------------------
// Binned scatter: 4 edges per thread, 4 lanes per edge. Four independent
// gathers in flight, then four REDs. Indices: two uint4 loads (4 x uint2).
// ---------------------------------------------------------------------------
__global__ void __launch_bounds__(256) scatter_k(
    const __half* __restrict__ xt, const uint2* __restrict__ esd,
    __half* __restrict__ agg, int ne, int nnodes)
{
    const int t = blockIdx.x * 256 + threadIdx.x;
    const int p = t >> 2;            // group of 4 edges
    const int q = t & 3;
    const int e0 = p * 4;
    if (e0 >= ne) return;

    const int o1 = __ldg(&g_off[1]), o2 = __ldg(&g_off[2]), o3 = __ldg(&g_off[3]);

    // Load 4 packed (src,dst) with two uint4 loads (broadcast in 4-lane group).
    uint2 sd[4];
    {
        const uint4 i0 = __ldg(reinterpret_cast<const uint4*>(esd + e0));
        sd[0] = make_uint2(i0.x, i0.y);
        sd[1] = make_uint2(i0.z, i0.w);
        if (e0 + 2 < ne) {
            const uint4 i1 = __ldg(reinterpret_cast<const uint4*>(esd + e0 + 2));
            sd[2] = make_uint2(i1.x, i1.y);
            sd[3] = make_uint2(i1.z, i1.w);
        } else {
            sd[2] = sd[0]; sd[3] = sd[0];
        }
    }

    const int nv = min(4, ne - e0);
    uint4 v[4];
    #pragma unroll
    for (int j = 0; j < 4; j++) {
        const int e = e0 + j;
        const int r = (e >= o1) + (e >= o2) + (e >= o3);
        if (j < nv)
            v[j] = *reinterpret_cast<const uint4*>(
                xt + (((size_t)r * nnodes + sd[j].x) << 5) + q * 8);
    }

    #pragma unroll
    for (int j = 0; j < 4; j++) {
        if (j < nv) {
            __half* ap = agg + ((size_t)sd[j].y << 5) + q * 8;
            asm volatile("red.global.add.noftz.v4.f16x2 [%0], {%1, %2, %3, %4};"
                         :: "l"(ap), "r"(v[j].x), "r"(v[j].y), "r"(v[j].z), "r"(v[j].w)
                         : "memory");
        }
    }
}

// ---------------------------------------------------------------------------
// Tensor-core transform; rel-major coalesced epilogue. zbuf: agg buffer to
// zero (agg1 in layer 1, agg2 in layer 2); layer 1 also resets counters.
// ---------------------------------------------------------------------------
template<bool PRE_ACT>
__global__ void __launch_bounds__(256) transform_k(
    const void* __restrict__ xin_, const float* __restrict__ W,
    const float* __restrict__ b, __half* __restrict__ xt,
    __half* __restrict__ zbuf, int nnodes)
{
    __shared__ __align__(16) unsigned char sm[TN * ST_STRIDE * 2]; // 34816 B
    __half* xh    = reinterpret_cast<__half*>(sm);
    __half* wh    = reinterpret_cast<__half*>(sm + 10240);
    __half* stage = reinterpret_cast<__half*>(sm);

    const int tid  = threadIdx.x;
    const int base = blockIdx.x * TN;

    {   // zero one agg buffer: nnodes*4 uint4, grid has nnodes*2 threads.
        const int gtid = blockIdx.x * 256 + tid;
        uint4* a = reinterpret_cast<uint4*>(zbuf);
        const uint4 zz = make_uint4(0u, 0u, 0u, 0u);
        a[gtid] = zz;
        a[gtid + nnodes * 2] = zz;
        if (!PRE_ACT && gtid == 0) {
            g_cnt4[0] = g_cnt4[1] = g_cnt4[2] = g_cnt4[3] = 0;
            g_done = 0u;
        }
    }

    // W smem: wh[d][r*32+o] = half(W[r][d][o]).
    for (int f = tid; f < 1024; f += 256) {
        const float4 v = reinterpret_cast<const float4*>(W)[f];
        const int r = f >> 8, d = (f >> 3) & 31, o4 = f & 7;
        __half* p = &wh[d * WH_STRIDE + r * 32 + o4 * 4];
        p[0] = __float2half_rn(v.x); p[1] = __float2half_rn(v.y);
        p[2] = __float2half_rn(v.z); p[3] = __float2half_rn(v.w);
    }

    // x tile.
    if (PRE_ACT) {
        const __half* xin = reinterpret_cast<const __half*>(xin_);
        for (int f = tid; f < TN * 4; f += 256) {
            const int i = f >> 2, kq = f & 3;
            const uint4 pk = *reinterpret_cast<const uint4*>(
                xin + (size_t)(base + i) * N_FEAT + kq * 8);
            const __half2* hp = reinterpret_cast<const __half2*>(&pk);
            const float4 b0 = __ldg(reinterpret_cast<const float4*>(b + kq * 8));
            const float4 b1 = __ldg(reinterpret_cast<const float4*>(b + kq * 8 + 4));
            const float bb[8] = {b0.x, b0.y, b0.z, b0.w, b1.x, b1.y, b1.z, b1.w};
            __half* d = &xh[i * XH_STRIDE + kq * 8];
            #pragma unroll
            for (int j = 0; j < 4; j++) {
                float2 fv = __half22float2(hp[j]);
                fv.x = fmaxf(fv.x + bb[j * 2 + 0], 0.f);
                fv.y = fmaxf(fv.y + bb[j * 2 + 1], 0.f);
                *reinterpret_cast<__half2*>(d + j * 2) = __floats2half2_rn(fv.x, fv.y);
            }
        }
    } else {
        const float4* xin4 = reinterpret_cast<const float4*>(
            reinterpret_cast<const float*>(xin_) + (size_t)base * N_FEAT);
        for (int f = tid; f < TN * 8; f += 256) {
            const float4 v = xin4[f];
            const int i = f >> 3, kq = f & 7;
            __half* d = &xh[i * XH_STRIDE + kq * 4];
            *reinterpret_cast<__half2*>(d)     = __floats2half2_rn(v.x, v.y);
            *reinterpret_cast<__half2*>(d + 2) = __floats2half2_rn(v.z, v.w);
        }
    }
    __syncthreads();

    const int w    = tid >> 5;
    const int lane = tid & 31;
    const int m0   = w * 16;

    uint32_t a[2][4];
    #pragma unroll
    for (int s = 0; s < 2; s++) {
        const int row = m0 + (lane & 15);
        const int col = s * 16 + ((lane >> 4) << 3);
        const uint32_t addr =
            (uint32_t)__cvta_generic_to_shared(&xh[row * XH_STRIDE + col]);
        asm volatile("ldmatrix.sync.aligned.m8n8.x4.shared.b16 {%0,%1,%2,%3}, [%4];"
                     : "=r"(a[s][0]), "=r"(a[s][1]), "=r"(a[s][2]), "=r"(a[s][3])
                     : "r"(addr));
    }

    float acc[16][4];
    #pragma unroll
    for (int j = 0; j < 16; j++)
        #pragma unroll
        for (int q = 0; q < 4; q++) acc[j][q] = 0.f;

    #pragma unroll
    for (int j = 0; j < 16; j++) {
        #pragma unroll
        for (int s = 0; s < 2; s++) {
            const int krow = s * 16 + (lane & 15);
            const uint32_t baddr =
                (uint32_t)__cvta_generic_to_shared(&wh[krow * WH_STRIDE + j * 8]);
            uint32_t b0, b1;
            asm volatile("ldmatrix.sync.aligned.m8n8.x2.trans.shared.b16 {%0,%1}, [%2];"
                         : "=r"(b0), "=r"(b1) : "r"(baddr));
            asm volatile(
                "mma.sync.aligned.m16n8k16.row.col.f32.f16.f16.f32 "
                "{%0,%1,%2,%3}, {%4,%5,%6,%7}, {%8,%9}, {%0,%1,%2,%3};"
                : "+f"(acc[j][0]), "+f"(acc[j][1]), "+f"(acc[j][2]), "+f"(acc[j][3])
                : "r"(a[s][0]), "r"(a[s][1]), "r"(a[s][2]), "r"(a[s][3]),
                  "r"(b0), "r"(b1));
        }
    }
    __syncthreads();

    const int g  = lane >> 2;
    const int t4 = lane & 3;
    #pragma unroll
    for (int j = 0; j < 16; j++) {
        *reinterpret_cast<__half2*>(&stage[(m0 + g) * ST_STRIDE + j * 8 + t4 * 2]) =
            __floats2half2_rn(acc[j][0], acc[j][1]);
        *reinterpret_cast<__half2*>(&stage[(m0 + g + 8) * ST_STRIDE + j * 8 + t4 * 2]) =
            __floats2half2_rn(acc[j][2], acc[j][3]);
    }
    __syncthreads();

    // Coalesced rel-major store.
    for (int f = tid; f < TN * 16; f += 256) {
        const int rel = f >> 9, row = (f >> 2) & 127, c4 = f & 3;
        const uint4 v = *reinterpret_cast<const uint4*>(
            &stage[row * ST_STRIDE + (rel * 4 + c4) * 8]);
        *reinterpret_cast<uint4*>(
            xt + (((size_t)rel * nnodes + base + row) << 5) + c4 * 8) = v;
    }
}

// ---------------------------------------------------------------------------
// Pool: out[g][c] = mean_{i<32} relu(agg2[g*32+i][c] + b[c]).
// ---------------------------------------------------------------------------
__global__ void __launch_bounds__(256) pool_k(
    const __half* __restrict__ agg, const float* __restrict__ b,
    float* __restrict__ out, int nnodes)
{
    const int t = blockIdx.x * blockDim.x + threadIdx.x;
    if (t >= nnodes) return;
    const int c = t & 31;
    const int g = t >> 5;
    const float bc = __ldg(b + c);
    const __half* p = agg + (size_t)g * 32 * N_FEAT + c;
    float s = 0.f;
    #pragma unroll
    for (int i = 0; i < 32; i++)
        s += fmaxf(__half2float(p[i * N_FEAT]) + bc, 0.f);
    out[t] = s * (1.0f / 32.0f);
}

// ---------------------------------------------------------------------------
// Launch order: 0 tf<0>(+zero agg1+counters), 1 hist, 2 reorder,
// 3 scatter1 (ncu capture slot), 4 tf<1>(+zero agg2), 5 scatter2, 6 pool.
// ---------------------------------------------------------------------------
extern "C" void kernel_launch(void* const* d_in, const int* in_sizes, int n_in,
                              void* d_out, int out_size)
{
    const float* x   = (const float*)d_in[0];
    const int*   src = (const int*)  d_in[1];
    const int*   dst = (const int*)  d_in[2];
    const int*   et  = (const int*)  d_in[3];
    const float* W   = (const float*)d_in[4];
    const float* b   = (const float*)d_in[5];

    const int nnodes = in_sizes[0] / N_FEAT;
    const int nedges = in_sizes[1];

    __half *xt, *agg1, *agg2; uint2 *esd;
    cudaGetSymbolAddress((void**)&xt,   g_xt);
    cudaGetSymbolAddress((void**)&agg1, g_agg1);
    cudaGetSymbolAddress((void**)&agg2, g_agg2);
    cudaGetSymbolAddress((void**)&esd,  g_esd);

    const int tf_blocks = nnodes / TN;
    const int eb_blocks = (nedges + 255) / 256;
    const int sc_blocks = (nedges + 255) / 256;   // 4 edges/thread, 4 lanes

    transform_k<false><<<tf_blocks, 256>>>(x, W, b, xt, agg1, nnodes);
    hist_k<<<eb_blocks, 256>>>(et, nedges);
    reorder_k<<<eb_blocks, 256>>>(src, dst, et, esd, nedges);
    scatter_k<<<sc_blocks, 256>>>(xt, esd, agg1, nedges, nnodes);
    transform_k<true><<<tf_blocks, 256>>>(agg1, W, b, xt, agg2, nnodes);
    scatter_k<<<sc_blocks, 256>>>(xt, esd, agg2, nedges, nnodes);
    pool_k<<<(nnodes + 255) / 256, 256>>>(agg2, b, (float*)d_out, nnodes);
    (void)n_in; (void)out_size;
}